// round 9
// baseline (speedup 1.0000x reference)
#include <cuda_runtime.h>
#include <cuda_fp16.h>
#include <cstdint>

#define B_      256
#define N_      1024
#define DIN     64
#define HID     256
#define DOUT    128
#define MT      64
#define TILES   16               // max tiles per batch (N_/MT)
#define THREADS 128
#define NCHUNKS 9                // k64 chunks: 1 (K=64) + 4 + 4

// smem layout (bytes)
#define SM_B     0                       // 2 buffers x 32768 (B: [256 n][128B = k64 fp16])
#define SM_BIAS  65536                   // 3 * 256 * 4
#define SM_POOL  68608                   // 4 * 256 * 4
#define SM_A     72704                   // A fp16: [64 m][512B row]
#define SM_BYTES (72704 + 32768)         // 105472  -> 2 CTAs/SM

__device__ float g_partial[B_ * TILES * HID];
__device__ __align__(16) __half g_wt[147456];
__device__ int g_cnt[B_];
__device__ int g_idx[B_ * N_];
#define WT1 0
#define WT2 16384
#define WT3 81920

// ---------------------------------------------------------------------------
// helpers
// ---------------------------------------------------------------------------
__device__ __forceinline__ uint32_t smem_u32(const void* p) {
    uint32_t a;
    asm("{ .reg .u64 t; cvta.to.shared.u64 t, %1; cvt.u32.u64 %0, t; }"
        : "=r"(a) : "l"(p));
    return a;
}
__device__ __forceinline__ void ldm4(uint32_t r[4], uint32_t addr) {
    asm volatile("ldmatrix.sync.aligned.m8n8.x4.shared.b16 {%0,%1,%2,%3}, [%4];"
                 : "=r"(r[0]), "=r"(r[1]), "=r"(r[2]), "=r"(r[3]) : "r"(addr));
}
__device__ __forceinline__ void mma16816(float c[4], const uint32_t a[4],
                                         uint32_t b0, uint32_t b1) {
    asm volatile(
        "mma.sync.aligned.m16n8k16.row.col.f32.f16.f16.f32 "
        "{%0,%1,%2,%3}, {%4,%5,%6,%7}, {%8,%9}, {%0,%1,%2,%3};"
        : "+f"(c[0]), "+f"(c[1]), "+f"(c[2]), "+f"(c[3])
        : "r"(a[0]), "r"(a[1]), "r"(a[2]), "r"(a[3]), "r"(b0), "r"(b1));
}
__device__ __forceinline__ void cpasync16(uint32_t dst, const void* src) {
    asm volatile("cp.async.ca.shared.global [%0], [%1], 16;" :: "r"(dst), "l"(src));
}
#define CP_COMMIT() asm volatile("cp.async.commit_group;" ::: "memory")
#define CP_WAIT(N)  asm volatile("cp.async.wait_group %0;" :: "n"(N) : "memory")

// pack two fp32 -> f16x2 (v0 -> first element in memory)
__device__ __forceinline__ uint32_t cvt_h2(float v0, float v1) {
    uint32_t r;
    asm("cvt.rn.f16x2.f32 %0, %1, %2;" : "=r"(r) : "f"(v1), "f"(v0));
    return r;
}

// ---------------------------------------------------------------------------
// prep: blocks 0..575 transpose+convert weights; blocks 576..831 compact mask
// ---------------------------------------------------------------------------
extern "C" __global__ void __launch_bounds__(256)
prep_all(const float* __restrict__ pw1, const float* __restrict__ pw2,
         const float* __restrict__ pw3, const int* __restrict__ mask)
{
    if (blockIdx.x < 576) {
        int i = blockIdx.x * 256 + threadIdx.x;
        if (i >= 147456) return;
        float v; int dst;
        if (i < 16384) {            // pw1 [64][256] -> [256][64]
            int k = i >> 8, n = i & 255;
            v = pw1[i]; dst = WT1 + n * 64 + k;
        } else if (i < 81920) {     // pw2 [256][256]
            int j = i - 16384; int k = j >> 8, n = j & 255;
            v = pw2[j]; dst = WT2 + n * 256 + k;
        } else {                    // pw3 [256][256]
            int j = i - 81920; int k = j >> 8, n = j & 255;
            v = pw3[j]; dst = WT3 + n * 256 + k;
        }
        g_wt[dst] = __float2half_rn(v);
    } else {
        const int b = blockIdx.x - 576, tid = threadIdx.x;
        const int lane = tid & 31, wid = tid >> 5;
        const int* mb = mask + b * N_;
        int v[4]; int c = 0;
#pragma unroll
        for (int i = 0; i < 4; i++) { v[i] = (mb[tid * 4 + i] != 0); c += v[i]; }
        int pre = c;
#pragma unroll
        for (int d = 1; d < 32; d <<= 1) {
            int t = __shfl_up_sync(0xffffffffu, pre, d);
            if (lane >= d) pre += t;
        }
        __shared__ int wsum[8];
        if (lane == 31) wsum[wid] = pre;
        __syncthreads();
        int wbase = 0;
#pragma unroll
        for (int w = 0; w < 8; w++)
            if (w < wid) wbase += wsum[w];
        int o = wbase + pre - c;
#pragma unroll
        for (int i = 0; i < 4; i++)
            if (v[i]) g_idx[b * N_ + (o++)] = tid * 4 + i;
        if (tid == 255) g_cnt[b] = wbase + pre;
    }
}

// ---------------------------------------------------------------------------
// issue one B chunk (k64) via cp.async into buffer gi&1
// row n = 128B (8 x 16B sub-chunks), sub-chunk c stored at c ^ (n&7)
// 128 threads -> each thread loads 2 rows
// ---------------------------------------------------------------------------
__device__ __forceinline__ void issue_chunk(int gi, uint32_t sb, int tid)
{
    const __half* w; int K, kc;
    if (gi == 0)     { w = g_wt + WT1; K = 64;  kc = 0; }
    else if (gi < 5) { w = g_wt + WT2; K = 256; kc = gi - 1; }
    else             { w = g_wt + WT3; K = 256; kc = gi - 5; }
    uint32_t base = sb + SM_B + (uint32_t)(gi & 1) * 32768u;
#pragma unroll
    for (int rr = 0; rr < 2; rr++) {
        int n = tid + rr * 128;
        uint32_t dst = base + (uint32_t)n * 128u;
        const char* src = (const char*)(w + (size_t)n * K + kc * 64);
#pragma unroll
        for (int c = 0; c < 8; c++)
            cpasync16(dst + ((uint32_t)(c ^ (n & 7)) << 4), src + c * 16);
    }
}

// epilogue store into A smem (fp16), swizzled
__device__ __forceinline__ void store_one(char* smem, int row, int chunk, int t,
                                          float v0, float v1)
{
    uint32_t h2 = cvt_h2(v0, v1);
    uint32_t off = (uint32_t)row * 512u + ((uint32_t)(chunk ^ (row & 7)) << 4) + t * 4;
    *(uint32_t*)(smem + SM_A + off) = h2;
}

// ---------------------------------------------------------------------------
// phi kernel: 64-row tiles, 4 warps, 2 CTAs/SM; fp16 x fp16 MMA + pool
// ---------------------------------------------------------------------------
extern "C" __global__ void __launch_bounds__(THREADS, 2)
phi_kernel(const float* __restrict__ x,
           const float* __restrict__ pb1, const float* __restrict__ pb2,
           const float* __restrict__ pb3)
{
    const int tile = blockIdx.x, b = blockIdx.y;
    const int cnt = g_cnt[b];
    if (tile * MT >= cnt) return;

    extern __shared__ char smem[];
    uint32_t sb = smem_u32(smem);
    const int tid = threadIdx.x, wid = tid >> 5, lane = tid & 31;
    const int m0 = wid * 16, gg = lane >> 2, t = lane & 3;

    // issue chunk 0 as early as possible
    issue_chunk(0, sb, tid);
    CP_COMMIT();

    ((float*)(smem + SM_BIAS))[tid]       = pb1[tid];
    ((float*)(smem + SM_BIAS))[128 + tid] = pb1[128 + tid];
    ((float*)(smem + SM_BIAS))[256 + tid] = pb2[tid];
    ((float*)(smem + SM_BIAS))[384 + tid] = pb2[128 + tid];
    ((float*)(smem + SM_BIAS))[512 + tid] = pb3[tid];
    ((float*)(smem + SM_BIAS))[640 + tid] = pb3[128 + tid];

    // ---- gather x rows -> A smem fp16; zero padding slots
    {
        int row = tid >> 1, half = tid & 1;        // 64 rows, 128 threads
        int slot = tile * MT + row;
        bool vld = slot < cnt;
        int r = vld ? g_idx[b * N_ + slot] : 0;
        const float4* src = (const float4*)(x +
            ((size_t)(b * N_ + r)) * DIN + half * 32);
#pragma unroll
        for (int c = 0; c < 4; c++) {
            int kc = half * 4 + c;   // 16B chunk index within row (0..7)
            uint32_t off = (uint32_t)row * 512u + ((uint32_t)(kc ^ (row & 7)) << 4);
            if (vld) {
                float4 a = src[c * 2];
                float4 d = src[c * 2 + 1];
                uint4 w;
                w.x = cvt_h2(a.x, a.y);
                w.y = cvt_h2(a.z, a.w);
                w.z = cvt_h2(d.x, d.y);
                w.w = cvt_h2(d.z, d.w);
                *(uint4*)(smem + SM_A + off) = w;
            } else {
                *(uint4*)(smem + SM_A + off) = make_uint4(0, 0, 0, 0);
            }
        }
    }

    float acc[32][4];
    int gi = 0;

    for (int l = 0; l < 3; l++) {
        const int nch = (l == 0) ? 1 : 4;
#pragma unroll
        for (int i = 0; i < 32; i++) {
            acc[i][0] = 0.f; acc[i][1] = 0.f; acc[i][2] = 0.f; acc[i][3] = 0.f;
        }
        for (int kc = 0; kc < nch; kc++) {
            if (gi + 1 < NCHUNKS) {
                issue_chunk(gi + 1, sb, tid);
                CP_COMMIT();
                CP_WAIT(1);              // chunk gi complete (gi+1 in flight)
            } else {
                CP_WAIT(0);
            }
            __syncthreads();             // publish chunk gi (+ A/epilogue writes)
            uint32_t bbase = sb + SM_B + (uint32_t)(gi & 1) * 32768u;
            uint32_t brow_ = (lane & 7) + ((lane >= 16) ? 8 : 0);
#pragma unroll
            for (int sc = 0; sc < 4; sc++) {
                int ks = kc * 4 + sc;        // k16 index within layer
                uint32_t arow = m0 + (lane & 15);
                uint32_t achk = 2 * ks + (lane >> 4);
                uint32_t aoff = arow * 512u + (((achk ^ (arow & 7))) << 4);
                uint32_t a[4];
                ldm4(a, sb + SM_A + aoff);

                uint32_t chi = 2 * sc + ((lane >> 3) & 1);   // 16B sub-chunk in B row

                uint32_t bh[2][4];
                {
                    uint32_t brow = brow_;
                    ldm4(bh[0], bbase + brow * 128u + ((chi ^ (brow & 7)) << 4));
                }
#pragma unroll
                for (int nt = 0; nt < 16; nt++) {
                    int cur = nt & 1, nxt = cur ^ 1;
                    if (nt < 15) {
                        uint32_t brow = (nt + 1) * 16 + brow_;
                        ldm4(bh[nxt], bbase + brow * 128u + ((chi ^ (brow & 7)) << 4));
                    }
                    mma16816(acc[2 * nt],     a, bh[cur][0], bh[cur][1]);
                    mma16816(acc[2 * nt + 1], a, bh[cur][2], bh[cur][3]);
                }
            }
            __syncthreads();             // compute done before buf reuse
            gi++;
        }

        if (l < 2) {
            const float* bias = (const float*)(smem + SM_BIAS) + l * 256;
            int r0 = m0 + gg, r1 = r0 + 8;
#pragma unroll
            for (int nt = 0; nt < 16; nt++) {
                int n0 = nt * 16;
                float b0 = bias[n0 + 2 * t],     float_b1 = bias[n0 + 2 * t + 1];
                float b2 = bias[n0 + 8 + 2 * t], b3 = bias[n0 + 8 + 2 * t + 1];
                store_one(smem, r0, 2 * nt, t,
                          fmaxf(acc[2 * nt][0] + b0, 0.f),
                          fmaxf(acc[2 * nt][1] + float_b1, 0.f));
                store_one(smem, r1, 2 * nt, t,
                          fmaxf(acc[2 * nt][2] + b0, 0.f),
                          fmaxf(acc[2 * nt][3] + float_b1, 0.f));
                store_one(smem, r0, 2 * nt + 1, t,
                          fmaxf(acc[2 * nt + 1][0] + b2, 0.f),
                          fmaxf(acc[2 * nt + 1][1] + b3, 0.f));
                store_one(smem, r1, 2 * nt + 1, t,
                          fmaxf(acc[2 * nt + 1][2] + b2, 0.f),
                          fmaxf(acc[2 * nt + 1][3] + b3, 0.f));
            }
            __syncwarp();   // each warp reads only its own 16 A rows next layer
        } else {
            const float* bias = (const float*)(smem + SM_BIAS) + 512;
            int r0 = m0 + gg, r1 = r0 + 8;
            float mv0 = (tile * MT + r0 < cnt) ? 1.f : 0.f;
            float mv1 = (tile * MT + r1 < cnt) ? 1.f : 0.f;
            float* pool = (float*)(smem + SM_POOL) + wid * 256;
#pragma unroll
            for (int nt = 0; nt < 16; nt++) {
                int n0 = nt * 16;
                float b0 = bias[n0 + 2 * t],     float_b1 = bias[n0 + 2 * t + 1];
                float b2 = bias[n0 + 8 + 2 * t], b3 = bias[n0 + 8 + 2 * t + 1];
                float s0 = mv0 * (acc[2 * nt][0] + b0) + mv1 * (acc[2 * nt][2] + b0);
                float s1 = mv0 * (acc[2 * nt][1] + float_b1) + mv1 * (acc[2 * nt][3] + float_b1);
                float s2 = mv0 * (acc[2 * nt + 1][0] + b2) + mv1 * (acc[2 * nt + 1][2] + b2);
                float s3 = mv0 * (acc[2 * nt + 1][1] + b3) + mv1 * (acc[2 * nt + 1][3] + b3);
#pragma unroll
                for (int d = 4; d < 32; d <<= 1) {
                    s0 += __shfl_xor_sync(0xffffffff, s0, d);
                    s1 += __shfl_xor_sync(0xffffffff, s1, d);
                    s2 += __shfl_xor_sync(0xffffffff, s2, d);
                    s3 += __shfl_xor_sync(0xffffffff, s3, d);
                }
                if (lane < 4) {
                    pool[n0 + 2 * t]         = s0;
                    pool[n0 + 2 * t + 1]     = s1;
                    pool[n0 + 8 + 2 * t]     = s2;
                    pool[n0 + 8 + 2 * t + 1] = s3;
                }
            }
            __syncthreads();
            // 128 threads reduce 4 warps' pools over 256 columns
#pragma unroll
            for (int h = 0; h < 2; h++) {
                int c = tid + h * 128;
                float s = 0.f;
#pragma unroll
                for (int w = 0; w < 4; w++)
                    s += ((const float*)(smem + SM_POOL))[w * 256 + c];
                g_partial[(b * TILES + tile) * HID + c] = s;
            }
        }
    }
}

// ---------------------------------------------------------------------------
// rho kernel: 512 threads, split-k partials; predicated unroll-16 gather
// ---------------------------------------------------------------------------
extern "C" __global__ void __launch_bounds__(512, 2)
rho_kernel(const float* __restrict__ rw1, const float* __restrict__ rb1,
           const float* __restrict__ rw2, const float* __restrict__ rb2,
           const float* __restrict__ rw3, const float* __restrict__ rb3,
           float* __restrict__ out)
{
    const int b   = blockIdx.x;
    const int tid = threadIdx.x;
    const int col = tid & 255, kh = tid >> 8;     // 2-way k split
    __shared__ float p[HID];
    __shared__ float o1[HID];
    __shared__ float part[512];

    const int cnt = g_cnt[b];
    const int ntile = (cnt + MT - 1) / MT;

    if (tid < 256) {
        float s = 0.f;
        const float* gp = g_partial + (size_t)b * TILES * HID + tid;
#pragma unroll
        for (int t = 0; t < TILES; t++) {
            float v = (t < ntile) ? gp[t * HID] : 0.f;
            s += v;
        }
        p[tid] = s;
    }
    __syncthreads();

    {
        const float* W = rw1 + (size_t)kh * 128 * HID + col;
        const float* pk = p + kh * 128;
        float a0 = 0.f, a1 = 0.f, a2 = 0.f, a3 = 0.f;
#pragma unroll 8
        for (int k = 0; k < 128; k += 4) {
            a0 = fmaf(pk[k],     W[(k)     * HID], a0);
            a1 = fmaf(pk[k + 1], W[(k + 1) * HID], a1);
            a2 = fmaf(pk[k + 2], W[(k + 2) * HID], a2);
            a3 = fmaf(pk[k + 3], W[(k + 3) * HID], a3);
        }
        part[tid] = (a0 + a1) + (a2 + a3);
    }
    __syncthreads();
    if (tid < 256)
        o1[tid] = fmaxf(part[tid] + part[tid + 256] + rb1[tid], 0.f);
    __syncthreads();

    {
        const float* W = rw2 + (size_t)kh * 128 * HID + col;
        const float* pk = o1 + kh * 128;
        float a0 = 0.f, a1 = 0.f, a2 = 0.f, a3 = 0.f;
#pragma unroll 8
        for (int k = 0; k < 128; k += 4) {
            a0 = fmaf(pk[k],     W[(k)     * HID], a0);
            a1 = fmaf(pk[k + 1], W[(k + 1) * HID], a1);
            a2 = fmaf(pk[k + 2], W[(k + 2) * HID], a2);
            a3 = fmaf(pk[k + 3], W[(k + 3) * HID], a3);
        }
        part[tid] = (a0 + a1) + (a2 + a3);
    }
    __syncthreads();
    if (tid < 256)
        p[tid] = fmaxf(part[tid] + part[tid + 256] + rb2[tid], 0.f);
    __syncthreads();

    {
        const int c3 = tid & 127, k4 = tid >> 7;
        const float* W = rw3 + (size_t)k4 * 64 * DOUT + c3;
        const float* pk = p + k4 * 64;
        float a0 = 0.f, a1 = 0.f, a2 = 0.f, a3 = 0.f;
#pragma unroll 8
        for (int k = 0; k < 64; k += 4) {
            a0 = fmaf(pk[k],     W[(k)     * DOUT], a0);
            a1 = fmaf(pk[k + 1], W[(k + 1) * DOUT], a1);
            a2 = fmaf(pk[k + 2], W[(k + 2) * DOUT], a2);
            a3 = fmaf(pk[k + 3], W[(k + 3) * DOUT], a3);
        }
        part[tid] = (a0 + a1) + (a2 + a3);
    }
    __syncthreads();
    if (tid < DOUT) {
        float a3 = part[tid] + part[tid + 128] + part[tid + 256] + part[tid + 384]
                 + rb3[tid];
        out[b * DOUT + tid] = (cnt > 0) ? a3 : 0.f;
    }
}

// ---------------------------------------------------------------------------
extern "C" void kernel_launch(void* const* d_in, const int* in_sizes, int n_in,
                              void* d_out, int out_size)
{
    const float* x    = (const float*)d_in[0];
    const int*   mask = (const int*)  d_in[1];
    const float* pw1  = (const float*)d_in[2];
    const float* pb1  = (const float*)d_in[3];
    const float* pw2  = (const float*)d_in[4];
    const float* pb2  = (const float*)d_in[5];
    const float* pw3  = (const float*)d_in[6];
    const float* pb3  = (const float*)d_in[7];
    const float* rw1  = (const float*)d_in[8];
    const float* rb1  = (const float*)d_in[9];
    const float* rw2  = (const float*)d_in[10];
    const float* rb2  = (const float*)d_in[11];
    const float* rw3  = (const float*)d_in[12];
    const float* rb3  = (const float*)d_in[13];
    float* out = (float*)d_out;

    cudaFuncSetAttribute(phi_kernel,
                         cudaFuncAttributeMaxDynamicSharedMemorySize, SM_BYTES);

    prep_all<<<832, 256>>>(pw1, pw2, pw3, mask);
    dim3 grid(TILES, B_);
    phi_kernel<<<grid, THREADS, SM_BYTES>>>(x, pb1, pb2, pb3);
    rho_kernel<<<B_, 512>>>(rw1, rb1, rw2, rb2, rw3, rb3, out);
}

// round 12
// speedup vs baseline: 1.2444x; 1.2444x over previous
#include <cuda_runtime.h>
#include <cuda_fp16.h>
#include <cstdint>

#define B_      256
#define N_      1024
#define DIN     64
#define HID     256
#define DOUT    128
#define MT      128
#define TILES   8                // max tiles per batch (N_/MT)
#define THREADS 256
#define NCHUNKS 9                // k64 chunks: 1 (K=64) + 4 + 4

// smem layout (bytes)
#define SM_B     0                       // 3 buffers x 32768 (B: [256 n][128B = k64 fp16])
#define SM_BIAS  98304                   // 3 * 256 * 4
#define SM_POOL  101376                  // 8 * 256 * 4 (reused as rho scratch)
#define SM_A     109568                  // A fp16: [128 m][512B row]
#define SM_BYTES (109568 + 65536)        // 175104

__device__ float g_partial[B_ * TILES * HID];
__device__ __align__(16) __half g_wt[147456];
__device__ int g_cnt[B_];
__device__ int g_idx[B_ * N_];
__device__ int g_done[B_];
#define WT1 0
#define WT2 16384
#define WT3 81920

// ---------------------------------------------------------------------------
// helpers
// ---------------------------------------------------------------------------
__device__ __forceinline__ uint32_t smem_u32(const void* p) {
    uint32_t a;
    asm("{ .reg .u64 t; cvta.to.shared.u64 t, %1; cvt.u32.u64 %0, t; }"
        : "=r"(a) : "l"(p));
    return a;
}
__device__ __forceinline__ void ldm4(uint32_t r[4], uint32_t addr) {
    asm volatile("ldmatrix.sync.aligned.m8n8.x4.shared.b16 {%0,%1,%2,%3}, [%4];"
                 : "=r"(r[0]), "=r"(r[1]), "=r"(r[2]), "=r"(r[3]) : "r"(addr));
}
__device__ __forceinline__ void mma16816(float c[4], const uint32_t a[4],
                                         uint32_t b0, uint32_t b1) {
    asm volatile(
        "mma.sync.aligned.m16n8k16.row.col.f32.f16.f16.f32 "
        "{%0,%1,%2,%3}, {%4,%5,%6,%7}, {%8,%9}, {%0,%1,%2,%3};"
        : "+f"(c[0]), "+f"(c[1]), "+f"(c[2]), "+f"(c[3])
        : "r"(a[0]), "r"(a[1]), "r"(a[2]), "r"(a[3]), "r"(b0), "r"(b1));
}
__device__ __forceinline__ void cpasync16(uint32_t dst, const void* src) {
    asm volatile("cp.async.ca.shared.global [%0], [%1], 16;" :: "r"(dst), "l"(src));
}
#define CP_COMMIT() asm volatile("cp.async.commit_group;" ::: "memory")
#define CP_WAIT(N)  asm volatile("cp.async.wait_group %0;" :: "n"(N) : "memory")

// pack two fp32 -> f16x2 (v0 -> first element in memory)
__device__ __forceinline__ uint32_t cvt_h2(float v0, float v1) {
    uint32_t r;
    asm("cvt.rn.f16x2.f32 %0, %1, %2;" : "=r"(r) : "f"(v1), "f"(v0));
    return r;
}

// ---------------------------------------------------------------------------
// prep: blocks 0..575 transpose+convert weights; blocks 576..831 compact mask,
// reset fan-in counters, zero outputs of empty batches
// ---------------------------------------------------------------------------
extern "C" __global__ void __launch_bounds__(256)
prep_all(const float* __restrict__ pw1, const float* __restrict__ pw2,
         const float* __restrict__ pw3, const int* __restrict__ mask,
         float* __restrict__ out)
{
    if (blockIdx.x < 576) {
        int i = blockIdx.x * 256 + threadIdx.x;
        if (i >= 147456) return;
        float v; int dst;
        if (i < 16384) {            // pw1 [64][256] -> [256][64]
            int k = i >> 8, n = i & 255;
            v = pw1[i]; dst = WT1 + n * 64 + k;
        } else if (i < 81920) {     // pw2 [256][256]
            int j = i - 16384; int k = j >> 8, n = j & 255;
            v = pw2[j]; dst = WT2 + n * 256 + k;
        } else {                    // pw3 [256][256]
            int j = i - 81920; int k = j >> 8, n = j & 255;
            v = pw3[j]; dst = WT3 + n * 256 + k;
        }
        g_wt[dst] = __float2half_rn(v);
    } else {
        const int b = blockIdx.x - 576, tid = threadIdx.x;
        const int lane = tid & 31, wid = tid >> 5;
        if (tid == 0) g_done[b] = 0;          // reset fan-in (every replay)
        const int* mb = mask + b * N_;
        int v[4]; int c = 0;
#pragma unroll
        for (int i = 0; i < 4; i++) { v[i] = (mb[tid * 4 + i] != 0); c += v[i]; }
        int pre = c;
#pragma unroll
        for (int d = 1; d < 32; d <<= 1) {
            int t = __shfl_up_sync(0xffffffffu, pre, d);
            if (lane >= d) pre += t;
        }
        __shared__ int wsum[8];
        if (lane == 31) wsum[wid] = pre;
        __syncthreads();
        int wbase = 0, total = 0;
#pragma unroll
        for (int w = 0; w < 8; w++) {
            if (w < wid) wbase += wsum[w];
            total += wsum[w];
        }
        int o = wbase + pre - c;
#pragma unroll
        for (int i = 0; i < 4; i++)
            if (v[i]) g_idx[b * N_ + (o++)] = tid * 4 + i;
        if (tid == 255) g_cnt[b] = total;
        // no phi CTA will run for empty batches -> zero output here
        if (total == 0 && tid < DOUT) out[b * DOUT + tid] = 0.f;
    }
}

// ---------------------------------------------------------------------------
// issue one B chunk (k64) via cp.async into ring buffer gi%3
// row n = 128B (8 x 16B sub-chunks), sub-chunk c stored at c ^ (n&7)
// ---------------------------------------------------------------------------
__device__ __forceinline__ void issue_chunk(int gi, uint32_t sb, int tid)
{
    const __half* w; int K, kc;
    if (gi == 0)     { w = g_wt + WT1; K = 64;  kc = 0; }
    else if (gi < 5) { w = g_wt + WT2; K = 256; kc = gi - 1; }
    else             { w = g_wt + WT3; K = 256; kc = gi - 5; }
    int n = tid;
    uint32_t dst = sb + SM_B + (uint32_t)(gi % 3) * 32768u + (uint32_t)n * 128u;
    const char* src = (const char*)(w + (size_t)n * K + kc * 64);
#pragma unroll
    for (int c = 0; c < 8; c++)
        cpasync16(dst + ((uint32_t)(c ^ (n & 7)) << 4), src + c * 16);
}

// epilogue store into A smem (fp16), swizzled
__device__ __forceinline__ void store_one(char* smem, int row, int chunk, int t,
                                          float v0, float v1)
{
    uint32_t h2 = cvt_h2(v0, v1);
    uint32_t off = (uint32_t)row * 512u + ((uint32_t)(chunk ^ (row & 7)) << 4) + t * 4;
    *(uint32_t*)(smem + SM_A + off) = h2;
}

// ---------------------------------------------------------------------------
// phi kernel: gathered valid rows; fp16 x fp16 MMA + pool + fan-in rho
// ---------------------------------------------------------------------------
extern "C" __global__ void __launch_bounds__(THREADS, 1)
phi_kernel(const float* __restrict__ x,
           const float* __restrict__ pb1, const float* __restrict__ pb2,
           const float* __restrict__ pb3,
           const float* __restrict__ rw1, const float* __restrict__ rb1,
           const float* __restrict__ rw2, const float* __restrict__ rb2,
           const float* __restrict__ rw3, const float* __restrict__ rb3,
           float* __restrict__ out)
{
    const int tile = blockIdx.x, b = blockIdx.y;
    const int cnt = g_cnt[b];
    if (tile * MT >= cnt) return;

    extern __shared__ char smem[];
    uint32_t sb = smem_u32(smem);
    const int tid = threadIdx.x, wid = tid >> 5, lane = tid & 31;
    const int m0 = wid * 16, gg = lane >> 2, t = lane & 3;

    // issue chunk 0 as early as possible
    issue_chunk(0, sb, tid);
    CP_COMMIT();

    ((float*)(smem + SM_BIAS))[tid]       = pb1[tid];
    ((float*)(smem + SM_BIAS))[256 + tid] = pb2[tid];
    ((float*)(smem + SM_BIAS))[512 + tid] = pb3[tid];

    // ---- gather x rows -> A smem fp16; zero padding slots
    {
        int row = tid >> 1, half = tid & 1;
        int slot = tile * MT + row;
        bool vld = slot < cnt;
        int r = vld ? g_idx[b * N_ + slot] : 0;
        const float4* src = (const float4*)(x +
            ((size_t)(b * N_ + r)) * DIN + half * 32);
#pragma unroll
        for (int c = 0; c < 4; c++) {
            int kc = half * 4 + c;   // 16B chunk index within row (0..7)
            uint32_t off = (uint32_t)row * 512u + ((uint32_t)(kc ^ (row & 7)) << 4);
            if (vld) {
                float4 a = src[c * 2];
                float4 d = src[c * 2 + 1];
                uint4 w;
                w.x = cvt_h2(a.x, a.y);
                w.y = cvt_h2(a.z, a.w);
                w.z = cvt_h2(d.x, d.y);
                w.w = cvt_h2(d.z, d.w);
                *(uint4*)(smem + SM_A + off) = w;
            } else {
                *(uint4*)(smem + SM_A + off) = make_uint4(0, 0, 0, 0);
            }
        }
    }

    float acc[32][4];
    int gi = 0;

    for (int l = 0; l < 3; l++) {
        const int nch = (l == 0) ? 1 : 4;
#pragma unroll
        for (int i = 0; i < 32; i++) {
            acc[i][0] = 0.f; acc[i][1] = 0.f; acc[i][2] = 0.f; acc[i][3] = 0.f;
        }
        for (int kc = 0; kc < nch; kc++) {
            if (gi + 1 < NCHUNKS) {
                issue_chunk(gi + 1, sb, tid);
                CP_COMMIT();
                CP_WAIT(1);              // chunk gi complete (gi+1 in flight)
            } else {
                CP_WAIT(0);
            }
            __syncthreads();             // publish chunk gi (+ A/epilogue writes)
            uint32_t bbase = sb + SM_B + (uint32_t)(gi % 3) * 32768u;
            uint32_t brow_ = (lane & 7) + ((lane >= 16) ? 8 : 0);
#pragma unroll
            for (int sc = 0; sc < 4; sc++) {
                int ks = kc * 4 + sc;        // k16 index within layer
                uint32_t arow = m0 + (lane & 15);
                uint32_t achk = 2 * ks + (lane >> 4);
                uint32_t aoff = arow * 512u + (((achk ^ (arow & 7))) << 4);
                uint32_t a[4];
                ldm4(a, sb + SM_A + aoff);

                uint32_t chi = 2 * sc + ((lane >> 3) & 1);   // 16B sub-chunk in B row

                uint32_t bh[2][4];
                {
                    uint32_t brow = brow_;
                    ldm4(bh[0], bbase + brow * 128u + ((chi ^ (brow & 7)) << 4));
                }
#pragma unroll
                for (int nt = 0; nt < 16; nt++) {
                    int cur = nt & 1, nxt = cur ^ 1;
                    if (nt < 15) {
                        uint32_t brow = (nt + 1) * 16 + brow_;
                        ldm4(bh[nxt], bbase + brow * 128u + ((chi ^ (brow & 7)) << 4));
                    }
                    mma16816(acc[2 * nt],     a, bh[cur][0], bh[cur][1]);
                    mma16816(acc[2 * nt + 1], a, bh[cur][2], bh[cur][3]);
                }
            }
            gi++;
        }

        if (l < 2) {
            const float* bias = (const float*)(smem + SM_BIAS) + l * 256;
            int r0 = m0 + gg, r1 = r0 + 8;
#pragma unroll
            for (int nt = 0; nt < 16; nt++) {
                int n0 = nt * 16;
                float b0 = bias[n0 + 2 * t],     b1 = bias[n0 + 2 * t + 1];
                float b2 = bias[n0 + 8 + 2 * t], b3 = bias[n0 + 8 + 2 * t + 1];
                store_one(smem, r0, 2 * nt, t,
                          fmaxf(acc[2 * nt][0] + b0, 0.f),
                          fmaxf(acc[2 * nt][1] + b1, 0.f));
                store_one(smem, r1, 2 * nt, t,
                          fmaxf(acc[2 * nt][2] + b0, 0.f),
                          fmaxf(acc[2 * nt][3] + b1, 0.f));
                store_one(smem, r0, 2 * nt + 1, t,
                          fmaxf(acc[2 * nt + 1][0] + b2, 0.f),
                          fmaxf(acc[2 * nt + 1][1] + b3, 0.f));
                store_one(smem, r1, 2 * nt + 1, t,
                          fmaxf(acc[2 * nt + 1][2] + b2, 0.f),
                          fmaxf(acc[2 * nt + 1][3] + b3, 0.f));
            }
            __syncwarp();   // each warp reads only its own 16 A rows next layer
        } else {
            const float* bias = (const float*)(smem + SM_BIAS) + 512;
            int r0 = m0 + gg, r1 = r0 + 8;
            float mv0 = (tile * MT + r0 < cnt) ? 1.f : 0.f;
            float mv1 = (tile * MT + r1 < cnt) ? 1.f : 0.f;
            float* pool = (float*)(smem + SM_POOL) + wid * 256;
#pragma unroll
            for (int nt = 0; nt < 16; nt++) {
                int n0 = nt * 16;
                float b0 = bias[n0 + 2 * t],     b1 = bias[n0 + 2 * t + 1];
                float b2 = bias[n0 + 8 + 2 * t], b3 = bias[n0 + 8 + 2 * t + 1];
                float s0 = mv0 * (acc[2 * nt][0] + b0) + mv1 * (acc[2 * nt][2] + b0);
                float s1 = mv0 * (acc[2 * nt][1] + b1) + mv1 * (acc[2 * nt][3] + b1);
                float s2 = mv0 * (acc[2 * nt + 1][0] + b2) + mv1 * (acc[2 * nt + 1][2] + b2);
                float s3 = mv0 * (acc[2 * nt + 1][1] + b3) + mv1 * (acc[2 * nt + 1][3] + b3);
#pragma unroll
                for (int d = 4; d < 32; d <<= 1) {
                    s0 += __shfl_xor_sync(0xffffffff, s0, d);
                    s1 += __shfl_xor_sync(0xffffffff, s1, d);
                    s2 += __shfl_xor_sync(0xffffffff, s2, d);
                    s3 += __shfl_xor_sync(0xffffffff, s3, d);
                }
                if (lane < 4) {
                    pool[n0 + 2 * t]         = s0;
                    pool[n0 + 2 * t + 1]     = s1;
                    pool[n0 + 8 + 2 * t]     = s2;
                    pool[n0 + 8 + 2 * t + 1] = s3;
                }
            }
            __syncthreads();
            float s = 0.f;
#pragma unroll
            for (int w = 0; w < 8; w++)
                s += ((const float*)(smem + SM_POOL))[w * 256 + tid];
            g_partial[(b * TILES + tile) * HID + tid] = s;
        }
    }

    // ================= fan-in: last CTA of batch b runs rho inline ==========
    const int ntile = (cnt + MT - 1) / MT;
    __threadfence();                     // release g_partial stores
    __shared__ int s_prev;
    if (tid == 0) s_prev = atomicAdd(&g_done[b], 1);
    __syncthreads();
    if (s_prev != ntile - 1) return;
    __threadfence();                     // acquire other CTAs' g_partial

    float* p_s  = (float*)(smem + SM_POOL);         // [256]
    float* o1v  = p_s + 256;                        // [256]
    float* part = o1v + 256;                        // [256]

    {
        float s = 0.f;
        const float* gp = g_partial + (size_t)b * TILES * HID + tid;
#pragma unroll
        for (int tt = 0; tt < TILES; tt++) {
            float v = (tt < ntile) ? gp[tt * HID] : 0.f;
            s += v;
        }
        __syncthreads();                 // pool-area reads above done? (p_s overwrite)
        p_s[tid] = s;
    }
    __syncthreads();

    // rho layer 1: 256 cols, full-k loop, 4 chains
    {
        const float* W = rw1 + tid;
        float a0 = 0.f, a1 = 0.f, a2 = 0.f, a3 = 0.f;
#pragma unroll 8
        for (int k = 0; k < HID; k += 4) {
            a0 = fmaf(p_s[k],     W[(k)     * HID], a0);
            a1 = fmaf(p_s[k + 1], W[(k + 1) * HID], a1);
            a2 = fmaf(p_s[k + 2], W[(k + 2) * HID], a2);
            a3 = fmaf(p_s[k + 3], W[(k + 3) * HID], a3);
        }
        o1v[tid] = fmaxf((a0 + a1) + (a2 + a3) + rb1[tid], 0.f);
    }
    __syncthreads();

    // rho layer 2
    {
        const float* W = rw2 + tid;
        float a0 = 0.f, a1 = 0.f, a2 = 0.f, a3 = 0.f;
#pragma unroll 8
        for (int k = 0; k < HID; k += 4) {
            a0 = fmaf(o1v[k],     W[(k)     * HID], a0);
            a1 = fmaf(o1v[k + 1], W[(k + 1) * HID], a1);
            a2 = fmaf(o1v[k + 2], W[(k + 2) * HID], a2);
            a3 = fmaf(o1v[k + 3], W[(k + 3) * HID], a3);
        }
        p_s[tid] = fmaxf((a0 + a1) + (a2 + a3) + rb2[tid], 0.f);
    }
    __syncthreads();

    // rho layer 3: 128 cols, 2-way k split
    {
        const int c3 = tid & 127, kh = tid >> 7;
        const float* W = rw3 + (size_t)kh * 128 * DOUT + c3;
        const float* pk = p_s + kh * 128;
        float a0 = 0.f, a1 = 0.f, a2 = 0.f, a3 = 0.f;
#pragma unroll 8
        for (int k = 0; k < 128; k += 4) {
            a0 = fmaf(pk[k],     W[(k)     * DOUT], a0);
            a1 = fmaf(pk[k + 1], W[(k + 1) * DOUT], a1);
            a2 = fmaf(pk[k + 2], W[(k + 2) * DOUT], a2);
            a3 = fmaf(pk[k + 3], W[(k + 3) * DOUT], a3);
        }
        part[tid] = (a0 + a1) + (a2 + a3);
    }
    __syncthreads();
    if (tid < DOUT)
        out[b * DOUT + tid] = part[tid] + part[tid + 128] + rb3[tid];
}

// ---------------------------------------------------------------------------
extern "C" void kernel_launch(void* const* d_in, const int* in_sizes, int n_in,
                              void* d_out, int out_size)
{
    const float* x    = (const float*)d_in[0];
    const int*   mask = (const int*)  d_in[1];
    const float* pw1  = (const float*)d_in[2];
    const float* pb1  = (const float*)d_in[3];
    const float* pw2  = (const float*)d_in[4];
    const float* pb2  = (const float*)d_in[5];
    const float* pw3  = (const float*)d_in[6];
    const float* pb3  = (const float*)d_in[7];
    const float* rw1  = (const float*)d_in[8];
    const float* rb1  = (const float*)d_in[9];
    const float* rw2  = (const float*)d_in[10];
    const float* rb2  = (const float*)d_in[11];
    const float* rw3  = (const float*)d_in[12];
    const float* rb3  = (const float*)d_in[13];
    float* out = (float*)d_out;

    cudaFuncSetAttribute(phi_kernel,
                         cudaFuncAttributeMaxDynamicSharedMemorySize, SM_BYTES);

    prep_all<<<832, 256>>>(pw1, pw2, pw3, mask, out);
    dim3 grid(TILES, B_);
    phi_kernel<<<grid, THREADS, SM_BYTES>>>(x, pb1, pb2, pb3,
                                            rw1, rb1, rw2, rb2, rw3, rb3, out);
}

// round 13
// speedup vs baseline: 1.6387x; 1.3169x over previous
#include <cuda_runtime.h>
#include <cuda_fp16.h>
#include <cstdint>

#define B_      256
#define N_      1024
#define DIN     64
#define HID     256
#define DOUT    128
#define MT      128
#define TILES   8                // max tiles per batch (N_/MT)
#define THREADS 256
#define NCHUNKS 9                // k64 chunks: 1 (K=64) + 4 + 4

// smem layout (bytes)
#define SM_B     0                       // 3 buffers x 32768 (B: [256 n][128B = k64 fp16])
#define SM_BIAS  98304                   // 3 * 256 * 4
#define SM_POOL  101376                  // 2 * 256 * 4
#define SM_A     109568                  // A fp16: [128 m][512B row]
#define SM_BYTES (109568 + 65536)        // 175104

__device__ float g_partial[B_ * TILES * HID];
__device__ __align__(16) __half g_wt[147456];
__device__ int g_cnt[B_];
__device__ int g_idx[B_ * N_];
#define WT1 0
#define WT2 16384
#define WT3 81920

// ---------------------------------------------------------------------------
// helpers
// ---------------------------------------------------------------------------
__device__ __forceinline__ uint32_t smem_u32(const void* p) {
    uint32_t a;
    asm("{ .reg .u64 t; cvta.to.shared.u64 t, %1; cvt.u32.u64 %0, t; }"
        : "=r"(a) : "l"(p));
    return a;
}
__device__ __forceinline__ void ldm4(uint32_t r[4], uint32_t addr) {
    asm volatile("ldmatrix.sync.aligned.m8n8.x4.shared.b16 {%0,%1,%2,%3}, [%4];"
                 : "=r"(r[0]), "=r"(r[1]), "=r"(r[2]), "=r"(r[3]) : "r"(addr));
}
__device__ __forceinline__ void mma16816(float c[4], const uint32_t a[4],
                                         uint32_t b0, uint32_t b1) {
    asm volatile(
        "mma.sync.aligned.m16n8k16.row.col.f32.f16.f16.f32 "
        "{%0,%1,%2,%3}, {%4,%5,%6,%7}, {%8,%9}, {%0,%1,%2,%3};"
        : "+f"(c[0]), "+f"(c[1]), "+f"(c[2]), "+f"(c[3])
        : "r"(a[0]), "r"(a[1]), "r"(a[2]), "r"(a[3]), "r"(b0), "r"(b1));
}
__device__ __forceinline__ void cpasync16(uint32_t dst, const void* src) {
    asm volatile("cp.async.ca.shared.global [%0], [%1], 16;" :: "r"(dst), "l"(src));
}
#define CP_COMMIT() asm volatile("cp.async.commit_group;" ::: "memory")
#define CP_WAIT(N)  asm volatile("cp.async.wait_group %0;" :: "n"(N) : "memory")

// pack two fp32 -> f16x2 (v0 -> first element in memory)
__device__ __forceinline__ uint32_t cvt_h2(float v0, float v1) {
    uint32_t r;
    asm("cvt.rn.f16x2.f32 %0, %1, %2;" : "=r"(r) : "f"(v1), "f"(v0));
    return r;
}

// ---------------------------------------------------------------------------
// prep: blocks 0..575 transpose+convert weights; blocks 576..831 compact mask
// ---------------------------------------------------------------------------
extern "C" __global__ void __launch_bounds__(256)
prep_all(const float* __restrict__ pw1, const float* __restrict__ pw2,
         const float* __restrict__ pw3, const int* __restrict__ mask)
{
    if (blockIdx.x < 576) {
        int i = blockIdx.x * 256 + threadIdx.x;
        if (i >= 147456) return;
        float v; int dst;
        if (i < 16384) {            // pw1 [64][256] -> [256][64]
            int k = i >> 8, n = i & 255;
            v = pw1[i]; dst = WT1 + n * 64 + k;
        } else if (i < 81920) {     // pw2 [256][256]
            int j = i - 16384; int k = j >> 8, n = j & 255;
            v = pw2[j]; dst = WT2 + n * 256 + k;
        } else {                    // pw3 [256][256]
            int j = i - 81920; int k = j >> 8, n = j & 255;
            v = pw3[j]; dst = WT3 + n * 256 + k;
        }
        g_wt[dst] = __float2half_rn(v);
    } else {
        const int b = blockIdx.x - 576, tid = threadIdx.x;
        const int lane = tid & 31, wid = tid >> 5;
        const int* mb = mask + b * N_;
        int v[4]; int c = 0;
#pragma unroll
        for (int i = 0; i < 4; i++) { v[i] = (mb[tid * 4 + i] != 0); c += v[i]; }
        int pre = c;
#pragma unroll
        for (int d = 1; d < 32; d <<= 1) {
            int t = __shfl_up_sync(0xffffffffu, pre, d);
            if (lane >= d) pre += t;
        }
        __shared__ int wsum[8];
        if (lane == 31) wsum[wid] = pre;
        __syncthreads();
        int wbase = 0;
#pragma unroll
        for (int w = 0; w < 8; w++)
            if (w < wid) wbase += wsum[w];
        int o = wbase + pre - c;
#pragma unroll
        for (int i = 0; i < 4; i++)
            if (v[i]) g_idx[b * N_ + (o++)] = tid * 4 + i;
        if (tid == 255) g_cnt[b] = wbase + pre;
    }
}

// ---------------------------------------------------------------------------
// issue one B chunk (k64) via cp.async into ring buffer gi%3
// row n = 128B (8 x 16B sub-chunks), sub-chunk c stored at c ^ (n&7)
// ---------------------------------------------------------------------------
__device__ __forceinline__ void issue_chunk(int gi, uint32_t sb, int tid)
{
    const __half* w; int K, kc;
    if (gi == 0)     { w = g_wt + WT1; K = 64;  kc = 0; }
    else if (gi < 5) { w = g_wt + WT2; K = 256; kc = gi - 1; }
    else             { w = g_wt + WT3; K = 256; kc = gi - 5; }
    int n = tid;
    uint32_t dst = sb + SM_B + (uint32_t)(gi % 3) * 32768u + (uint32_t)n * 128u;
    const char* src = (const char*)(w + (size_t)n * K + kc * 64);
#pragma unroll
    for (int c = 0; c < 8; c++)
        cpasync16(dst + ((uint32_t)(c ^ (n & 7)) << 4), src + c * 16);
}

// epilogue store into A smem (fp16), swizzled. chunk = 8-col (16B) group idx
__device__ __forceinline__ void store_one(char* smem, int row, int chunk, int t,
                                          float v0, float v1)
{
    uint32_t h2 = cvt_h2(v0, v1);
    uint32_t off = (uint32_t)row * 512u + ((uint32_t)(chunk ^ (row & 7)) << 4) + t * 4;
    *(uint32_t*)(smem + SM_A + off) = h2;
}

// ---------------------------------------------------------------------------
// phi kernel: gathered valid rows; fp16 x fp16 MMA, 2(M)x4(N) warp grid
// ---------------------------------------------------------------------------
extern "C" __global__ void __launch_bounds__(THREADS, 1)
phi_kernel(const float* __restrict__ x,
           const float* __restrict__ pb1, const float* __restrict__ pb2,
           const float* __restrict__ pb3)
{
    const int tile = blockIdx.x, b = blockIdx.y;
    const int cnt = g_cnt[b];
    if (tile * MT >= cnt) return;

    extern __shared__ char smem[];
    uint32_t sb = smem_u32(smem);
    const int tid = threadIdx.x, wid = tid >> 5, lane = tid & 31;
    const int mw = wid >> 2, nw = wid & 3;       // 2 x 4 warp grid
    const int gg = lane >> 2, t = lane & 3;

    // issue chunk 0 as early as possible
    issue_chunk(0, sb, tid);
    CP_COMMIT();

    ((float*)(smem + SM_BIAS))[tid]       = pb1[tid];
    ((float*)(smem + SM_BIAS))[256 + tid] = pb2[tid];
    ((float*)(smem + SM_BIAS))[512 + tid] = pb3[tid];

    // ---- gather x rows -> A smem fp16; zero padding slots
    {
        int row = tid >> 1, half = tid & 1;
        int slot = tile * MT + row;
        bool vld = slot < cnt;
        int r = vld ? g_idx[b * N_ + slot] : 0;
        const float4* src = (const float4*)(x +
            ((size_t)(b * N_ + r)) * DIN + half * 32);
#pragma unroll
        for (int c = 0; c < 4; c++) {
            int kc = half * 4 + c;   // 16B chunk index within row (0..7)
            uint32_t off = (uint32_t)row * 512u + ((uint32_t)(kc ^ (row & 7)) << 4);
            if (vld) {
                float4 a = src[c * 2];
                float4 d = src[c * 2 + 1];
                uint4 w;
                w.x = cvt_h2(a.x, a.y);
                w.y = cvt_h2(a.z, a.w);
                w.z = cvt_h2(d.x, d.y);
                w.w = cvt_h2(d.z, d.w);
                *(uint4*)(smem + SM_A + off) = w;
            } else {
                *(uint4*)(smem + SM_A + off) = make_uint4(0, 0, 0, 0);
            }
        }
    }

    // acc[i*8 + j2]: m16 tile i (rows mw*64+i*16), n8 tile j2 (cols nw*64+j2*8)
    float acc[32][4];
    int gi = 0;

    for (int l = 0; l < 3; l++) {
        const int nch = (l == 0) ? 1 : 4;
#pragma unroll
        for (int i = 0; i < 32; i++) {
            acc[i][0] = 0.f; acc[i][1] = 0.f; acc[i][2] = 0.f; acc[i][3] = 0.f;
        }
        for (int kc = 0; kc < nch; kc++) {
            if (gi + 1 < NCHUNKS) {
                issue_chunk(gi + 1, sb, tid);
                CP_COMMIT();
                CP_WAIT(1);              // chunk gi complete (gi+1 in flight)
            } else {
                CP_WAIT(0);
            }
            __syncthreads();             // publish chunk gi (+ A/epilogue writes)
            uint32_t bbase = sb + SM_B + (uint32_t)(gi % 3) * 32768u;
            uint32_t brow_ = (lane & 7) + ((lane >= 16) ? 8 : 0);
#pragma unroll
            for (int sc = 0; sc < 4; sc++) {
                int ks = kc * 4 + sc;        // k16 index within layer
                uint32_t achk = 2 * ks + (lane >> 4);

                uint32_t af[4][4];
#pragma unroll
                for (int i = 0; i < 4; i++) {
                    uint32_t arow = mw * 64 + i * 16 + (lane & 15);
                    uint32_t aoff = arow * 512u + ((achk ^ (arow & 7)) << 4);
                    ldm4(af[i], sb + SM_A + aoff);
                }

                uint32_t chi = 2 * sc + ((lane >> 3) & 1);
                uint32_t bf[4][4];
#pragma unroll
                for (int j = 0; j < 4; j++) {
                    uint32_t brow = (nw * 4 + j) * 16 + brow_;
                    ldm4(bf[j], bbase + brow * 128u + ((chi ^ (brow & 7)) << 4));
                }

#pragma unroll
                for (int i = 0; i < 4; i++)
#pragma unroll
                    for (int j = 0; j < 4; j++) {
                        mma16816(acc[i * 8 + 2 * j],     af[i], bf[j][0], bf[j][1]);
                        mma16816(acc[i * 8 + 2 * j + 1], af[i], bf[j][2], bf[j][3]);
                    }
            }
            gi++;
        }

        if (l < 2) {
            // epilogue: bias + relu + fp16 -> A smem (warp owns rows mw*64.. x cols nw*64..)
            const float* bias = (const float*)(smem + SM_BIAS) + l * 256;
#pragma unroll
            for (int i = 0; i < 4; i++) {
                int r0 = mw * 64 + i * 16 + gg, r1 = r0 + 8;
#pragma unroll
                for (int j2 = 0; j2 < 8; j2++) {
                    int n0 = nw * 64 + j2 * 8;
                    float b0 = bias[n0 + 2 * t], b1 = bias[n0 + 2 * t + 1];
                    store_one(smem, r0, nw * 8 + j2, t,
                              fmaxf(acc[i * 8 + j2][0] + b0, 0.f),
                              fmaxf(acc[i * 8 + j2][1] + b1, 0.f));
                    store_one(smem, r1, nw * 8 + j2, t,
                              fmaxf(acc[i * 8 + j2][2] + b0, 0.f),
                              fmaxf(acc[i * 8 + j2][3] + b1, 0.f));
                }
            }
            // cross-warp A visibility is ordered by the next chunk's __syncthreads
        } else {
            // masked pool over this warp's 64 rows for its 64 cols
            const float* bias = (const float*)(smem + SM_BIAS) + 512;
            float mv0[4], mv1[4];
#pragma unroll
            for (int i = 0; i < 4; i++) {
                int r0 = tile * MT + mw * 64 + i * 16 + gg;
                mv0[i] = (r0 < cnt) ? 1.f : 0.f;
                mv1[i] = (r0 + 8 < cnt) ? 1.f : 0.f;
            }
            float* pool = (float*)(smem + SM_POOL) + mw * 256;
#pragma unroll
            for (int j2 = 0; j2 < 8; j2++) {
                int n0 = nw * 64 + j2 * 8;
                float b0 = bias[n0 + 2 * t], b1 = bias[n0 + 2 * t + 1];
                float s0 = 0.f, s1 = 0.f;
#pragma unroll
                for (int i = 0; i < 4; i++) {
                    s0 += mv0[i] * (acc[i * 8 + j2][0] + b0)
                        + mv1[i] * (acc[i * 8 + j2][2] + b0);
                    s1 += mv0[i] * (acc[i * 8 + j2][1] + b1)
                        + mv1[i] * (acc[i * 8 + j2][3] + b1);
                }
#pragma unroll
                for (int d = 4; d < 32; d <<= 1) {   // reduce over gg
                    s0 += __shfl_xor_sync(0xffffffff, s0, d);
                    s1 += __shfl_xor_sync(0xffffffff, s1, d);
                }
                if (lane < 4) {
                    pool[n0 + 2 * t]     = s0;
                    pool[n0 + 2 * t + 1] = s1;
                }
            }
            __syncthreads();
            float s = ((const float*)(smem + SM_POOL))[tid]
                    + ((const float*)(smem + SM_POOL))[256 + tid];
            g_partial[(b * TILES + tile) * HID + tid] = s;
        }
    }
}

// ---------------------------------------------------------------------------
// rho kernel: 512 threads, split-k partials; predicated unroll-8 gather
// ---------------------------------------------------------------------------
extern "C" __global__ void __launch_bounds__(512, 2)
rho_kernel(const float* __restrict__ rw1, const float* __restrict__ rb1,
           const float* __restrict__ rw2, const float* __restrict__ rb2,
           const float* __restrict__ rw3, const float* __restrict__ rb3,
           float* __restrict__ out)
{
    const int b   = blockIdx.x;
    const int tid = threadIdx.x;
    const int col = tid & 255, kh = tid >> 8;     // 2-way k split
    __shared__ float p[HID];
    __shared__ float o1[HID];
    __shared__ float part[512];

    const int cnt = g_cnt[b];
    const int ntile = (cnt + MT - 1) / MT;

    if (tid < 256) {
        float s = 0.f;
        const float* gp = g_partial + (size_t)b * TILES * HID + tid;
#pragma unroll
        for (int t = 0; t < TILES; t++) {
            float v = (t < ntile) ? gp[t * HID] : 0.f;
            s += v;
        }
        p[tid] = s;
    }
    __syncthreads();

    {
        const float* W = rw1 + (size_t)kh * 128 * HID + col;
        const float* pk = p + kh * 128;
        float a0 = 0.f, a1 = 0.f, a2 = 0.f, a3 = 0.f;
#pragma unroll 8
        for (int k = 0; k < 128; k += 4) {
            a0 = fmaf(pk[k],     W[(k)     * HID], a0);
            a1 = fmaf(pk[k + 1], W[(k + 1) * HID], a1);
            a2 = fmaf(pk[k + 2], W[(k + 2) * HID], a2);
            a3 = fmaf(pk[k + 3], W[(k + 3) * HID], a3);
        }
        part[tid] = (a0 + a1) + (a2 + a3);
    }
    __syncthreads();
    if (tid < 256)
        o1[tid] = fmaxf(part[tid] + part[tid + 256] + rb1[tid], 0.f);
    __syncthreads();

    {
        const float* W = rw2 + (size_t)kh * 128 * HID + col;
        const float* pk = o1 + kh * 128;
        float a0 = 0.f, a1 = 0.f, a2 = 0.f, a3 = 0.f;
#pragma unroll 8
        for (int k = 0; k < 128; k += 4) {
            a0 = fmaf(pk[k],     W[(k)     * HID], a0);
            a1 = fmaf(pk[k + 1], W[(k + 1) * HID], a1);
            a2 = fmaf(pk[k + 2], W[(k + 2) * HID], a2);
            a3 = fmaf(pk[k + 3], W[(k + 3) * HID], a3);
        }
        part[tid] = (a0 + a1) + (a2 + a3);
    }
    __syncthreads();
    if (tid < 256)
        p[tid] = fmaxf(part[tid] + part[tid + 256] + rb2[tid], 0.f);
    __syncthreads();

    {
        const int c3 = tid & 127, k4 = tid >> 7;
        const float* W = rw3 + (size_t)k4 * 64 * DOUT + c3;
        const float* pk = p + k4 * 64;
        float a0 = 0.f, a1 = 0.f, a2 = 0.f, a3 = 0.f;
#pragma unroll 8
        for (int k = 0; k < 64; k += 4) {
            a0 = fmaf(pk[k],     W[(k)     * DOUT], a0);
            a1 = fmaf(pk[k + 1], W[(k + 1) * DOUT], a1);
            a2 = fmaf(pk[k + 2], W[(k + 2) * DOUT], a2);
            a3 = fmaf(pk[k + 3], W[(k + 3) * DOUT], a3);
        }
        part[tid] = (a0 + a1) + (a2 + a3);
    }
    __syncthreads();
    if (tid < DOUT) {
        float a3 = part[tid] + part[tid + 128] + part[tid + 256] + part[tid + 384]
                 + rb3[tid];
        out[b * DOUT + tid] = (cnt > 0) ? a3 : 0.f;
    }
}

// ---------------------------------------------------------------------------
extern "C" void kernel_launch(void* const* d_in, const int* in_sizes, int n_in,
                              void* d_out, int out_size)
{
    const float* x    = (const float*)d_in[0];
    const int*   mask = (const int*)  d_in[1];
    const float* pw1  = (const float*)d_in[2];
    const float* pb1  = (const float*)d_in[3];
    const float* pw2  = (const float*)d_in[4];
    const float* pb2  = (const float*)d_in[5];
    const float* pw3  = (const float*)d_in[6];
    const float* pb3  = (const float*)d_in[7];
    const float* rw1  = (const float*)d_in[8];
    const float* rb1  = (const float*)d_in[9];
    const float* rw2  = (const float*)d_in[10];
    const float* rb2  = (const float*)d_in[11];
    const float* rw3  = (const float*)d_in[12];
    const float* rb3  = (const float*)d_in[13];
    float* out = (float*)d_out;

    cudaFuncSetAttribute(phi_kernel,
                         cudaFuncAttributeMaxDynamicSharedMemorySize, SM_BYTES);

    prep_all<<<832, 256>>>(pw1, pw2, pw3, mask);
    dim3 grid(TILES, B_);
    phi_kernel<<<grid, THREADS, SM_BYTES>>>(x, pb1, pb2, pb3);
    rho_kernel<<<B_, 512>>>(rw1, rb1, rw2, rb2, rw3, rb3, out);
}

// round 14
// speedup vs baseline: 1.6570x; 1.0111x over previous
#include <cuda_runtime.h>
#include <cuda_fp16.h>
#include <cstdint>

#define B_      256
#define N_      1024
#define DIN     64
#define HID     256
#define DOUT    128
#define MT      128
#define MAXTILE 2048             // worst case: all rows valid
#define SLOTS   10               // max tiles overlapping one batch (<=9) + pad
#define THREADS 256
#define NCHUNKS 9                // k64 chunks: 1 (K=64) + 4 + 4

// smem layout (bytes)
#define SM_B     0                       // 3 buffers x 32768 (B: [256 n][128B = k64 fp16])
#define SM_BIAS  98304                   // 2 * 256 * 4 (pb1, pb2)
#define SM_A     109568                  // A fp16: [128 m][512B row]
#define SM_ROWB  173056                  // 128 ints (row batch ids, epilogue-3)
#define SM_BYTES (109568 + 65536)        // 175104
// epilogue-3 pool buffer reuses bytes [0, 135168): 128 rows x 264 floats

__device__ float g_partial[B_ * SLOTS * HID];
__device__ __align__(16) __half g_wt[147456];
__device__ int g_cnt[B_];
__device__ int g_idx[B_ * N_];
__device__ int g_src[B_ * N_];           // global compacted rows: (b<<10)|n
__device__ int g_base[B_];               // b*SLOTS - (off_b>>7)
__device__ int g_total;
#define WT1 0
#define WT2 16384
#define WT3 81920

// ---------------------------------------------------------------------------
// helpers
// ---------------------------------------------------------------------------
__device__ __forceinline__ uint32_t smem_u32(const void* p) {
    uint32_t a;
    asm("{ .reg .u64 t; cvta.to.shared.u64 t, %1; cvt.u32.u64 %0, t; }"
        : "=r"(a) : "l"(p));
    return a;
}
__device__ __forceinline__ void ldm4(uint32_t r[4], uint32_t addr) {
    asm volatile("ldmatrix.sync.aligned.m8n8.x4.shared.b16 {%0,%1,%2,%3}, [%4];"
                 : "=r"(r[0]), "=r"(r[1]), "=r"(r[2]), "=r"(r[3]) : "r"(addr));
}
__device__ __forceinline__ void mma16816(float c[4], const uint32_t a[4],
                                         uint32_t b0, uint32_t b1) {
    asm volatile(
        "mma.sync.aligned.m16n8k16.row.col.f32.f16.f16.f32 "
        "{%0,%1,%2,%3}, {%4,%5,%6,%7}, {%8,%9}, {%0,%1,%2,%3};"
        : "+f"(c[0]), "+f"(c[1]), "+f"(c[2]), "+f"(c[3])
        : "r"(a[0]), "r"(a[1]), "r"(a[2]), "r"(a[3]), "r"(b0), "r"(b1));
}
__device__ __forceinline__ void cpasync16(uint32_t dst, const void* src) {
    asm volatile("cp.async.ca.shared.global [%0], [%1], 16;" :: "r"(dst), "l"(src));
}
#define CP_COMMIT() asm volatile("cp.async.commit_group;" ::: "memory")
#define CP_WAIT(N)  asm volatile("cp.async.wait_group %0;" :: "n"(N) : "memory")

// pack two fp32 -> f16x2 (v0 -> first element in memory)
__device__ __forceinline__ uint32_t cvt_h2(float v0, float v1) {
    uint32_t r;
    asm("cvt.rn.f16x2.f32 %0, %1, %2;" : "=r"(r) : "f"(v1), "f"(v0));
    return r;
}

// ---------------------------------------------------------------------------
// prep_all: blocks 0..575 weights; 576..831 per-batch compaction;
//           832..1087 zero g_partial
// ---------------------------------------------------------------------------
extern "C" __global__ void __launch_bounds__(256)
prep_all(const float* __restrict__ pw1, const float* __restrict__ pw2,
         const float* __restrict__ pw3, const int* __restrict__ mask)
{
    if (blockIdx.x < 576) {
        int i = blockIdx.x * 256 + threadIdx.x;
        if (i >= 147456) return;
        float v; int dst;
        if (i < 16384) {            // pw1 [64][256] -> [256][64]
            int k = i >> 8, n = i & 255;
            v = pw1[i]; dst = WT1 + n * 64 + k;
        } else if (i < 81920) {     // pw2 [256][256]
            int j = i - 16384; int k = j >> 8, n = j & 255;
            v = pw2[j]; dst = WT2 + n * 256 + k;
        } else {                    // pw3 [256][256]
            int j = i - 81920; int k = j >> 8, n = j & 255;
            v = pw3[j]; dst = WT3 + n * 256 + k;
        }
        g_wt[dst] = __float2half_rn(v);
    } else if (blockIdx.x < 832) {
        const int b = blockIdx.x - 576, tid = threadIdx.x;
        const int lane = tid & 31, wid = tid >> 5;
        const int* mb = mask + b * N_;
        int v[4]; int c = 0;
#pragma unroll
        for (int i = 0; i < 4; i++) { v[i] = (mb[tid * 4 + i] != 0); c += v[i]; }
        int pre = c;
#pragma unroll
        for (int d = 1; d < 32; d <<= 1) {
            int t = __shfl_up_sync(0xffffffffu, pre, d);
            if (lane >= d) pre += t;
        }
        __shared__ int wsum[8];
        if (lane == 31) wsum[wid] = pre;
        __syncthreads();
        int wbase = 0;
#pragma unroll
        for (int w = 0; w < 8; w++)
            if (w < wid) wbase += wsum[w];
        int o = wbase + pre - c;
#pragma unroll
        for (int i = 0; i < 4; i++)
            if (v[i]) g_idx[b * N_ + (o++)] = tid * 4 + i;
        if (tid == 255) g_cnt[b] = wbase + pre;
    } else {
        // zero g_partial slots for batch (blockIdx.x - 832)
        const int b = blockIdx.x - 832;
        float4* dst = (float4*)(g_partial + (size_t)b * SLOTS * HID);
        // SLOTS*HID/4 = 640 float4
        for (int i = threadIdx.x; i < 640; i += 256)
            dst[i] = make_float4(0.f, 0.f, 0.f, 0.f);
    }
}

// ---------------------------------------------------------------------------
// prep3: every block redundantly scans g_cnt; block b scatters its rows
// ---------------------------------------------------------------------------
extern "C" __global__ void __launch_bounds__(256)
prep3_scatter()
{
    const int b = blockIdx.x, tid = threadIdx.x;
    const int lane = tid & 31, wid = tid >> 5;
    __shared__ int s_excl[256];
    __shared__ int wsum[8];

    int c = g_cnt[tid];
    int pre = c;
#pragma unroll
    for (int d = 1; d < 32; d <<= 1) {
        int t = __shfl_up_sync(0xffffffffu, pre, d);
        if (lane >= d) pre += t;
    }
    if (lane == 31) wsum[wid] = pre;
    __syncthreads();
    int wbase = 0, total = 0;
#pragma unroll
    for (int w = 0; w < 8; w++) {
        if (w < wid) wbase += wsum[w];
        total += wsum[w];
    }
    s_excl[tid] = wbase + pre - c;       // exclusive prefix of batch tid
    __syncthreads();

    const int off = s_excl[b];
    const int cnt = g_cnt[b];
    if (tid == 0) {
        g_base[b] = b * SLOTS - (off >> 7);
        if (b == 0) g_total = total;
    }
    for (int i = tid; i < cnt; i += 256)
        g_src[off + i] = (b << 10) | g_idx[b * N_ + i];
}

// ---------------------------------------------------------------------------
// issue one B chunk (k64) via cp.async into ring buffer gi%3
// ---------------------------------------------------------------------------
__device__ __forceinline__ void issue_chunk(int gi, uint32_t sb, int tid)
{
    const __half* w; int K, kc;
    if (gi == 0)     { w = g_wt + WT1; K = 64;  kc = 0; }
    else if (gi < 5) { w = g_wt + WT2; K = 256; kc = gi - 1; }
    else             { w = g_wt + WT3; K = 256; kc = gi - 5; }
    int n = tid;
    uint32_t dst = sb + SM_B + (uint32_t)(gi % 3) * 32768u + (uint32_t)n * 128u;
    const char* src = (const char*)(w + (size_t)n * K + kc * 64);
#pragma unroll
    for (int c = 0; c < 8; c++)
        cpasync16(dst + ((uint32_t)(c ^ (n & 7)) << 4), src + c * 16);
}

// epilogue store into A smem (fp16), swizzled. chunk = 8-col (16B) group idx
__device__ __forceinline__ void store_one(char* smem, int row, int chunk, int t,
                                          float v0, float v1)
{
    uint32_t h2 = cvt_h2(v0, v1);
    uint32_t off = (uint32_t)row * 512u + ((uint32_t)(chunk ^ (row & 7)) << 4) + t * 4;
    *(uint32_t*)(smem + SM_A + off) = h2;
}

// ---------------------------------------------------------------------------
// phi kernel: globally compacted rows; fp16 MMA, 2(M)x4(N) warp grid;
// segmented pool epilogue
// ---------------------------------------------------------------------------
extern "C" __global__ void __launch_bounds__(THREADS, 1)
phi_kernel(const float* __restrict__ x,
           const float* __restrict__ pb1, const float* __restrict__ pb2,
           const float* __restrict__ pb3)
{
    const int tile = blockIdx.x;
    const int T = g_total;
    if (tile * MT >= T) return;

    extern __shared__ char smem[];
    uint32_t sb = smem_u32(smem);
    const int tid = threadIdx.x, wid = tid >> 5, lane = tid & 31;
    const int mw = wid >> 2, nw = wid & 3;       // 2 x 4 warp grid
    const int gg = lane >> 2, t = lane & 3;

    // issue chunk 0 as early as possible
    issue_chunk(0, sb, tid);
    CP_COMMIT();

    ((float*)(smem + SM_BIAS))[tid]       = pb1[tid];
    ((float*)(smem + SM_BIAS))[256 + tid] = pb2[tid];

    // ---- gather compacted rows -> A smem fp16; zero padding slots
    {
        int row = tid >> 1, half = tid & 1;
        int g = tile * MT + row;
        bool vld = g < T;
        int src_rn = vld ? g_src[g] : 0;         // (b<<10)|n
        const float4* src = (const float4*)(x +
            ((size_t)src_rn) * DIN + half * 32);
#pragma unroll
        for (int c = 0; c < 4; c++) {
            int kc = half * 4 + c;   // 16B chunk index within row (0..7)
            uint32_t off = (uint32_t)row * 512u + ((uint32_t)(kc ^ (row & 7)) << 4);
            if (vld) {
                float4 a = src[c * 2];
                float4 d = src[c * 2 + 1];
                uint4 w;
                w.x = cvt_h2(a.x, a.y);
                w.y = cvt_h2(a.z, a.w);
                w.z = cvt_h2(d.x, d.y);
                w.w = cvt_h2(d.z, d.w);
                *(uint4*)(smem + SM_A + off) = w;
            } else {
                *(uint4*)(smem + SM_A + off) = make_uint4(0, 0, 0, 0);
            }
        }
    }

    // acc[i*8 + j2]: m16 tile i (rows mw*64+i*16), n8 tile j2 (cols nw*64+j2*8)
    float acc[32][4];
    int gi = 0;

    for (int l = 0; l < 3; l++) {
        const int nch = (l == 0) ? 1 : 4;
#pragma unroll
        for (int i = 0; i < 32; i++) {
            acc[i][0] = 0.f; acc[i][1] = 0.f; acc[i][2] = 0.f; acc[i][3] = 0.f;
        }
        for (int kc = 0; kc < nch; kc++) {
            if (gi + 1 < NCHUNKS) {
                issue_chunk(gi + 1, sb, tid);
                CP_COMMIT();
                CP_WAIT(1);              // chunk gi complete (gi+1 in flight)
            } else {
                CP_WAIT(0);
            }
            __syncthreads();             // publish chunk gi (+ A/epilogue writes)
            uint32_t bbase = sb + SM_B + (uint32_t)(gi % 3) * 32768u;
            uint32_t brow_ = (lane & 7) + ((lane >= 16) ? 8 : 0);
#pragma unroll
            for (int sc = 0; sc < 4; sc++) {
                int ks = kc * 4 + sc;        // k16 index within layer
                uint32_t achk = 2 * ks + (lane >> 4);

                uint32_t af[4][4];
#pragma unroll
                for (int i = 0; i < 4; i++) {
                    uint32_t arow = mw * 64 + i * 16 + (lane & 15);
                    uint32_t aoff = arow * 512u + ((achk ^ (arow & 7)) << 4);
                    ldm4(af[i], sb + SM_A + aoff);
                }

                uint32_t chi = 2 * sc + ((lane >> 3) & 1);
                uint32_t bf[4][4];
#pragma unroll
                for (int j = 0; j < 4; j++) {
                    uint32_t brow = (nw * 4 + j) * 16 + brow_;
                    ldm4(bf[j], bbase + brow * 128u + ((chi ^ (brow & 7)) << 4));
                }

#pragma unroll
                for (int i = 0; i < 4; i++)
#pragma unroll
                    for (int j = 0; j < 4; j++) {
                        mma16816(acc[i * 8 + 2 * j],     af[i], bf[j][0], bf[j][1]);
                        mma16816(acc[i * 8 + 2 * j + 1], af[i], bf[j][2], bf[j][3]);
                    }
            }
            gi++;
        }

        if (l < 2) {
            // epilogue: bias + relu + fp16 -> A smem (warp owns rows mw*64.. x cols nw*64..)
            const float* bias = (const float*)(smem + SM_BIAS) + l * 256;
#pragma unroll
            for (int i = 0; i < 4; i++) {
                int r0 = mw * 64 + i * 16 + gg, r1 = r0 + 8;
#pragma unroll
                for (int j2 = 0; j2 < 8; j2++) {
                    int n0 = nw * 64 + j2 * 8;
                    float b0 = bias[n0 + 2 * t], b1 = bias[n0 + 2 * t + 1];
                    store_one(smem, r0, nw * 8 + j2, t,
                              fmaxf(acc[i * 8 + j2][0] + b0, 0.f),
                              fmaxf(acc[i * 8 + j2][1] + b1, 0.f));
                    store_one(smem, r1, nw * 8 + j2, t,
                              fmaxf(acc[i * 8 + j2][2] + b0, 0.f),
                              fmaxf(acc[i * 8 + j2][3] + b1, 0.f));
                }
            }
            // cross-warp A visibility is ordered by the next chunk's __syncthreads
        } else {
            // ---- segmented pool epilogue ----
            __syncthreads();             // all MMAs done: B buffers reusable
            float* pb = (float*)smem;    // pool buffer: 128 rows x 264 floats
#pragma unroll
            for (int j2 = 0; j2 < 8; j2++) {
                int n0 = nw * 64 + j2 * 8 + 2 * t;
                float b0 = __ldg(pb3 + n0), b1 = __ldg(pb3 + n0 + 1);
#pragma unroll
                for (int i = 0; i < 4; i++) {
                    int r0 = mw * 64 + i * 16 + gg, r1 = r0 + 8;
                    *(float2*)(pb + r0 * 264 + n0) =
                        make_float2(acc[i * 8 + j2][0] + b0, acc[i * 8 + j2][1] + b1);
                    *(float2*)(pb + r1 * 264 + n0) =
                        make_float2(acc[i * 8 + j2][2] + b0, acc[i * 8 + j2][3] + b1);
                }
            }
            int* rowb = (int*)(smem + SM_ROWB);
            if (tid < MT) {
                int g = tile * MT + tid;
                rowb[tid] = (g < T) ? (g_src[g] >> 10) : -1;
            }
            __syncthreads();
            // per-column segmented reduction over 128 rows
            {
                const int c = tid;
                float s = 0.f;
                int curb = rowb[0];
#pragma unroll 16
                for (int r = 0; r < MT; r++) {
                    int bb = rowb[r];
                    if (bb != curb) {
                        if (curb >= 0)
                            g_partial[(g_base[curb] + tile) * HID + c] = s;
                        s = 0.f;
                        curb = bb;
                    }
                    s += pb[r * 264 + c];
                }
                if (curb >= 0)
                    g_partial[(g_base[curb] + tile) * HID + c] = s;
            }
        }
    }
}

// ---------------------------------------------------------------------------
// rho kernel: 512 threads, split-k partials; sum all SLOTS partials
// ---------------------------------------------------------------------------
extern "C" __global__ void __launch_bounds__(512, 2)
rho_kernel(const float* __restrict__ rw1, const float* __restrict__ rb1,
           const float* __restrict__ rw2, const float* __restrict__ rb2,
           const float* __restrict__ rw3, const float* __restrict__ rb3,
           float* __restrict__ out)
{
    const int b   = blockIdx.x;
    const int tid = threadIdx.x;
    const int col = tid & 255, kh = tid >> 8;     // 2-way k split
    __shared__ float p[HID];
    __shared__ float o1[HID];
    __shared__ float part[512];

    const int cnt = g_cnt[b];

    if (tid < 256) {
        float s = 0.f;
        const float* gp = g_partial + (size_t)b * SLOTS * HID + tid;
#pragma unroll
        for (int t = 0; t < SLOTS; t++)
            s += gp[t * HID];
        p[tid] = s;
    }
    __syncthreads();

    {
        const float* W = rw1 + (size_t)kh * 128 * HID + col;
        const float* pk = p + kh * 128;
        float a0 = 0.f, a1 = 0.f, a2 = 0.f, a3 = 0.f;
#pragma unroll 8
        for (int k = 0; k < 128; k += 4) {
            a0 = fmaf(pk[k],     W[(k)     * HID], a0);
            a1 = fmaf(pk[k + 1], W[(k + 1) * HID], a1);
            a2 = fmaf(pk[k + 2], W[(k + 2) * HID], a2);
            a3 = fmaf(pk[k + 3], W[(k + 3) * HID], a3);
        }
        part[tid] = (a0 + a1) + (a2 + a3);
    }
    __syncthreads();
    if (tid < 256)
        o1[tid] = fmaxf(part[tid] + part[tid + 256] + rb1[tid], 0.f);
    __syncthreads();

    {
        const float* W = rw2 + (size_t)kh * 128 * HID + col;
        const float* pk = o1 + kh * 128;
        float a0 = 0.f, a1 = 0.f, a2 = 0.f, a3 = 0.f;
#pragma unroll 8
        for (int k = 0; k < 128; k += 4) {
            a0 = fmaf(pk[k],     W[(k)     * HID], a0);
            a1 = fmaf(pk[k + 1], W[(k + 1) * HID], a1);
            a2 = fmaf(pk[k + 2], W[(k + 2) * HID], a2);
            a3 = fmaf(pk[k + 3], W[(k + 3) * HID], a3);
        }
        part[tid] = (a0 + a1) + (a2 + a3);
    }
    __syncthreads();
    if (tid < 256)
        p[tid] = fmaxf(part[tid] + part[tid + 256] + rb2[tid], 0.f);
    __syncthreads();

    {
        const int c3 = tid & 127, k4 = tid >> 7;
        const float* W = rw3 + (size_t)k4 * 64 * DOUT + c3;
        const float* pk = p + k4 * 64;
        float a0 = 0.f, a1 = 0.f, a2 = 0.f, a3 = 0.f;
#pragma unroll 8
        for (int k = 0; k < 64; k += 4) {
            a0 = fmaf(pk[k],     W[(k)     * DOUT], a0);
            a1 = fmaf(pk[k + 1], W[(k + 1) * DOUT], a1);
            a2 = fmaf(pk[k + 2], W[(k + 2) * DOUT], a2);
            a3 = fmaf(pk[k + 3], W[(k + 3) * DOUT], a3);
        }
        part[tid] = (a0 + a1) + (a2 + a3);
    }
    __syncthreads();
    if (tid < DOUT) {
        float a3 = part[tid] + part[tid + 128] + part[tid + 256] + part[tid + 384]
                 + rb3[tid];
        out[b * DOUT + tid] = (cnt > 0) ? a3 : 0.f;
    }
}

// ---------------------------------------------------------------------------
extern "C" void kernel_launch(void* const* d_in, const int* in_sizes, int n_in,
                              void* d_out, int out_size)
{
    const float* x    = (const float*)d_in[0];
    const int*   mask = (const int*)  d_in[1];
    const float* pw1  = (const float*)d_in[2];
    const float* pb1  = (const float*)d_in[3];
    const float* pw2  = (const float*)d_in[4];
    const float* pb2  = (const float*)d_in[5];
    const float* pw3  = (const float*)d_in[6];
    const float* pb3  = (const float*)d_in[7];
    const float* rw1  = (const float*)d_in[8];
    const float* rb1  = (const float*)d_in[9];
    const float* rw2  = (const float*)d_in[10];
    const float* rb2  = (const float*)d_in[11];
    const float* rw3  = (const float*)d_in[12];
    const float* rb3  = (const float*)d_in[13];
    float* out = (float*)d_out;

    cudaFuncSetAttribute(phi_kernel,
                         cudaFuncAttributeMaxDynamicSharedMemorySize, SM_BYTES);

    prep_all<<<1088, 256>>>(pw1, pw2, pw3, mask);
    prep3_scatter<<<256, 256>>>();
    phi_kernel<<<MAXTILE, THREADS, SM_BYTES>>>(x, pb1, pb2, pb3);
    rho_kernel<<<B_, 512>>>(rw1, rb1, rw2, rb2, rw3, rb3, out);
}